// round 15
// baseline (speedup 1.0000x reference)
#include <cuda_runtime.h>
#include <cuda_fp16.h>
#include <cstdint>

// Problem constants (fixed by the reference)
#define NN   100000
#define NE   1600000
#define CH   128
#define NG   512
#define TOT  (NE + NN)          // edges + self loops
#define SCAN_T 1024
#define NB_SCAN ((NN + SCAN_T - 1) / SCAN_T)   // 98
#define GROWS 64                 // GEMM rows per block
#define NWFRAG (3 * 8 * 16 * 32) // layers x kc(8) x nt(16) x lanes(32)

// ---------------- scratch (static __device__ allocations; allowed) ----------
__device__ __half g_th[(size_t)NN * CH];   // post-GEMM features, dinv-prescaled (fp16)
__device__ __half g_hh[(size_t)NN * CH];   // post-aggregation features (fp16)
__device__ float g_pool[NG * CH];          // global_add_pool accumulator
__device__ float g_dinv[NN];
__device__ int   g_cnt[NN];
__device__ int   g_rowptr[NN + 1];
__device__ int   g_fill[NN];
__device__ int   g_edge_src[TOT];          // src index only (dinv factored out)
__device__ int   g_scan_flag[NB_SCAN];     // 0=none, 1=aggregate, 2=inclusive
__device__ int   g_agg_val[NB_SCAN];
__device__ int   g_inc_val[NB_SCAN];
__device__ int   g_ei64;                   // 1 if edge_index is int64, else int32
__device__ int   g_b64;                    // 1 if batch is int64, else int32
// B fragments for mma.m16n8k16.f16 in register order:
// index = ((layer*8 + kc)*16 + nt)*32 + lane -> uint2 {b0(half2), b1(half2)}
__device__ uint2 g_wfrag[NWFRAG];

// ---------------- dtype-agnostic index load ---------------------------------
__device__ __forceinline__ int ld_idx(const void* __restrict__ p, int i, int is64) {
    if (is64) return (int)((const long long*)p)[i];
    return ((const int*)p)[i];
}

// ---------------- fused pre kernel -------------------------------------------
__global__ void k_pre(const float* __restrict__ Ws,
                      const int* __restrict__ ei32,
                      const int* __restrict__ b32) {
    int idx = blockIdx.x * blockDim.x + threadIdx.x;

    if (idx < NN) g_cnt[idx] = 1;            // self loop contributes 1 to degree
    if (idx < NG * CH) g_pool[idx] = 0.0f;
    if (idx < NB_SCAN) g_scan_flag[idx] = 0;

    if (idx < NWFRAG) {
        int lane = idx & 31;
        int nt   = (idx >> 5) & 15;
        int kc   = (idx >> 9) & 7;
        int l    = idx >> 12;
        const float* W = Ws + (size_t)l * CH * CH;
        int tg = lane & 3, g = lane >> 2;
        int k0 = kc * 16 + 2 * tg;
        int n  = nt * 8 + g;
        __half2 b0 = __floats2half2_rn(W[(size_t)k0 * CH + n],
                                       W[(size_t)(k0 + 1) * CH + n]);
        __half2 b1 = __floats2half2_rn(W[(size_t)(k0 + 8) * CH + n],
                                       W[(size_t)(k0 + 9) * CH + n]);
        g_wfrag[idx] = make_uint2(*(uint32_t*)&b0, *(uint32_t*)&b1);
    }

    // dtype detection: int64 of small values has zero odd 32-bit words.
    if (blockIdx.x == 0 && threadIdx.x < 64) {
        int w = threadIdx.x >> 5, l = threadIdx.x & 31;
        int nz = 0;
        if (w == 0) {
            #pragma unroll
            for (int k = 0; k < 2; k++)
                nz |= (ei32[2 * (l * 2 + k) + 1] != 0);
            unsigned m = __ballot_sync(0xffffffffu, nz);
            if (l == 0) g_ei64 = (m == 0u);
        } else {
            #pragma unroll
            for (int k = 0; k < 2; k++)
                nz |= (b32[2 * (25000 + l * 2 + k) + 1] != 0);
            unsigned m = __ballot_sync(0xffffffffu, nz);
            if (l == 0) g_b64 = (m == 0u);
        }
    }
}

// ---------------- degree count: 4 edges/thread, vectorized loads -------------
__global__ void k_degree(const void* __restrict__ ei) {
    int base = (blockIdx.x * blockDim.x + threadIdx.x) * 4;
    if (base >= NE) return;
    int is64 = g_ei64;
    if (base + 4 <= NE) {
        int d0, d1, d2, d3;
        if (is64) {
            const longlong2* p = (const longlong2*)((const long long*)ei + NE + base);
            longlong2 v0 = p[0], v1 = p[1];
            d0 = (int)v0.x; d1 = (int)v0.y; d2 = (int)v1.x; d3 = (int)v1.y;
        } else {
            int4 v = *(const int4*)((const int*)ei + NE + base);
            d0 = v.x; d1 = v.y; d2 = v.z; d3 = v.w;
        }
        atomicAdd(&g_cnt[d0], 1);
        atomicAdd(&g_cnt[d1], 1);
        atomicAdd(&g_cnt[d2], 1);
        atomicAdd(&g_cnt[d3], 1);
    } else {
        for (int e = base; e < NE; e++)
            atomicAdd(&g_cnt[ld_idx(ei, NE + e, is64)], 1);
    }
}

// ---------------- single-pass scan (decoupled lookback) ----------------------
__global__ __launch_bounds__(SCAN_T)
void k_scan_all() {
    __shared__ int ws[32];
    __shared__ int s_prefix;
    int tid = threadIdx.x, b = blockIdx.x;
    int i = b * SCAN_T + tid;
    int v = (i < NN) ? g_cnt[i] : 0;
    float dinv = rsqrtf((float)v);
    if (i < NN) g_dinv[i] = dinv;

    int lane = tid & 31, wid = tid >> 5;
    int x = v;
    #pragma unroll
    for (int o = 1; o < 32; o <<= 1) {
        int y = __shfl_up_sync(0xffffffffu, x, o);
        if (lane >= o) x += y;
    }
    if (lane == 31) ws[wid] = x;
    __syncthreads();
    if (wid == 0) {
        int s = ws[lane];
        #pragma unroll
        for (int o = 1; o < 32; o <<= 1) {
            int y = __shfl_up_sync(0xffffffffu, s, o);
            if (lane >= o) s += y;
        }
        ws[lane] = s;
    }
    __syncthreads();
    int off = wid ? ws[wid - 1] : 0;
    int incl = x + off;                 // inclusive within block
    int total = ws[31];                 // block aggregate

    if (b == 0) {
        if (tid == 0) {
            g_inc_val[0] = total;
            __threadfence();
            atomicExch(&g_scan_flag[0], 2);
            s_prefix = 0;
        }
    } else {
        if (tid == 0) {
            g_agg_val[b] = total;
            __threadfence();
            atomicExch(&g_scan_flag[b], 1);
        }
        if (tid < 32) {                 // warp-parallel lookback
            int sum = 0, p = b - 1;
            while (true) {
                int idxp = p - lane;
                int f = 2, vv = 0;
                if (idxp >= 0) {
                    f = atomicAdd(&g_scan_flag[idxp], 0);
                    if (f == 2)      vv = atomicAdd(&g_inc_val[idxp], 0);
                    else if (f == 1) vv = atomicAdd(&g_agg_val[idxp], 0);
                }
                unsigned pm = __ballot_sync(0xffffffffu, f == 2);
                unsigned am = __ballot_sync(0xffffffffu, f >= 1);
                if (pm) {
                    int L = __ffs(pm) - 1;
                    unsigned below = (L == 0) ? 0u : ((1u << L) - 1u);
                    if ((am & below) == below) {
                        int c = (lane <= L) ? vv : 0;
                        #pragma unroll
                        for (int o = 16; o; o >>= 1)
                            c += __shfl_xor_sync(0xffffffffu, c, o);
                        sum += c;
                        break;
                    }
                } else if (am == 0xffffffffu) {
                    int c = vv;
                    #pragma unroll
                    for (int o = 16; o; o >>= 1)
                        c += __shfl_xor_sync(0xffffffffu, c, o);
                    sum += c;
                    p -= 32;
                }
            }
            if (lane == 0) {
                s_prefix = sum;
                g_inc_val[b] = sum + total;
                __threadfence();
                atomicExch(&g_scan_flag[b], 2);
            }
        }
    }
    __syncthreads();

    int prefix = s_prefix;
    if (i < NN) {
        int rp = prefix + incl - v;     // exclusive global prefix
        g_rowptr[i] = rp;
        g_edge_src[rp] = i;             // self-loop edge: src = i
        g_fill[i] = rp + 1;
    }
    if (i == 0) g_rowptr[NN] = TOT;
}

// ---------------- CSR fill: 4 edges/thread, vectorized loads -----------------
__global__ void k_fill(const void* __restrict__ ei) {
    int base = (blockIdx.x * blockDim.x + threadIdx.x) * 4;
    if (base >= NE) return;
    int is64 = g_ei64;
    if (base + 4 <= NE) {
        int s0, s1, s2, s3, d0, d1, d2, d3;
        if (is64) {
            const longlong2* ps = (const longlong2*)((const long long*)ei + base);
            const longlong2* pd = (const longlong2*)((const long long*)ei + NE + base);
            longlong2 u0 = ps[0], u1 = ps[1];
            longlong2 v0 = pd[0], v1 = pd[1];
            s0 = (int)u0.x; s1 = (int)u0.y; s2 = (int)u1.x; s3 = (int)u1.y;
            d0 = (int)v0.x; d1 = (int)v0.y; d2 = (int)v1.x; d3 = (int)v1.y;
        } else {
            int4 u = *(const int4*)((const int*)ei + base);
            int4 v = *(const int4*)((const int*)ei + NE + base);
            s0 = u.x; s1 = u.y; s2 = u.z; s3 = u.w;
            d0 = v.x; d1 = v.y; d2 = v.z; d3 = v.w;
        }
        int p0 = atomicAdd(&g_fill[d0], 1);
        int p1 = atomicAdd(&g_fill[d1], 1);
        int p2 = atomicAdd(&g_fill[d2], 1);
        int p3 = atomicAdd(&g_fill[d3], 1);
        g_edge_src[p0] = s0;
        g_edge_src[p1] = s1;
        g_edge_src[p2] = s2;
        g_edge_src[p3] = s3;
    } else {
        for (int e = base; e < NE; e++) {
            int s = ld_idx(ei, e, is64);
            int d = ld_idx(ei, NE + e, is64);
            int pos = atomicAdd(&g_fill[d], 1);
            g_edge_src[pos] = s;
        }
    }
}

// ---------------- GEMM via fp16 tensor cores (m16n8k16, fp32 accum) ----------
// g_th[N,128] = fp16(dinv_row * (A[N,128] @ W[128,128])); A==nullptr -> g_hh.
__global__ __launch_bounds__(128)
void k_gemm_tc(const float* __restrict__ A_, int layer) {
    __shared__ __half sA[GROWS][136];
    int tid = threadIdx.x, wid = tid >> 5, lane = tid & 31;
    int row0 = blockIdx.x * GROWS;

    if (A_ != nullptr) {
        #pragma unroll
        for (int i = tid; i < GROWS * 16; i += 128) {
            int r = i >> 4, c8 = (i & 15) << 3;
            int gr = row0 + r;
            __half2 h0, h1, h2, h3;
            if (gr < NN) {
                const float* src = A_ + (size_t)gr * CH + c8;
                float4 v0 = *(const float4*)(src);
                float4 v1 = *(const float4*)(src + 4);
                h0 = __floats2half2_rn(v0.x, v0.y);
                h1 = __floats2half2_rn(v0.z, v0.w);
                h2 = __floats2half2_rn(v1.x, v1.y);
                h3 = __floats2half2_rn(v1.z, v1.w);
            } else {
                h0 = h1 = h2 = h3 = __floats2half2_rn(0.f, 0.f);
            }
            uint4 u;
            u.x = *(uint32_t*)&h0; u.y = *(uint32_t*)&h1;
            u.z = *(uint32_t*)&h2; u.w = *(uint32_t*)&h3;
            *(uint4*)&sA[r][c8] = u;
        }
    } else {
        const __half* hb = (const __half*)g_hh;
        #pragma unroll
        for (int i = tid; i < GROWS * 16; i += 128) {
            int r = i >> 4, c8 = (i & 15) << 3;
            int gr = row0 + r;
            uint4 u = make_uint4(0, 0, 0, 0);
            if (gr < NN) u = *(const uint4*)(hb + (size_t)gr * CH + c8);
            *(uint4*)&sA[r][c8] = u;
        }
    }
    __syncthreads();

    int mrow = wid * 16;
    int g  = lane >> 2;        // group id 0..7
    int tg = lane & 3;         // thread-in-group

    float acc[16][4];
    #pragma unroll
    for (int nt = 0; nt < 16; nt++)
        #pragma unroll
        for (int j = 0; j < 4; j++) acc[nt][j] = 0.f;

    const uint2* __restrict__ wbase = g_wfrag + ((size_t)layer * 128) * 32 + lane;

    #pragma unroll
    for (int kc = 0; kc < 8; kc++) {
        int k0 = kc * 16 + 2 * tg;
        uint32_t a0 = *(const uint32_t*)&sA[mrow + g][k0];
        uint32_t a1 = *(const uint32_t*)&sA[mrow + g + 8][k0];
        uint32_t a2 = *(const uint32_t*)&sA[mrow + g][k0 + 8];
        uint32_t a3 = *(const uint32_t*)&sA[mrow + g + 8][k0 + 8];
        const uint2* wk = wbase + (size_t)(kc * 16) * 32;
        #pragma unroll
        for (int nt = 0; nt < 16; nt++) {
            uint2 b = wk[(size_t)nt * 32];
            asm volatile(
                "mma.sync.aligned.m16n8k16.row.col.f32.f16.f16.f32 "
                "{%0,%1,%2,%3}, {%4,%5,%6,%7}, {%8,%9}, {%0,%1,%2,%3};"
                : "+f"(acc[nt][0]), "+f"(acc[nt][1]),
                  "+f"(acc[nt][2]), "+f"(acc[nt][3])
                : "r"(a0), "r"(a1), "r"(a2), "r"(a3), "r"(b.x), "r"(b.y));
        }
    }

    // epilogue: scale rows by dinv and store fp16
    int gr0 = row0 + mrow + g;
    int gr1 = gr0 + 8;
    float dv0 = (gr0 < NN) ? g_dinv[gr0] : 0.f;
    float dv1 = (gr1 < NN) ? g_dinv[gr1] : 0.f;
    #pragma unroll
    for (int nt = 0; nt < 16; nt++) {
        int col = nt * 8 + 2 * tg;
        if (gr0 < NN)
            *(__half2*)&g_th[(size_t)gr0 * CH + col] =
                __floats2half2_rn(dv0 * acc[nt][0], dv0 * acc[nt][1]);
        if (gr1 < NN)
            *(__half2*)&g_th[(size_t)gr1 * CH + col] =
                __floats2half2_rn(dv1 * acc[nt][2], dv1 * acc[nt][3]);
    }
}

// ---------------- aggregation: h[i] = ReLU(dinv_i * sum_j t'[src_j] + b) ----
template <bool LAST>
__global__ __launch_bounds__(256)
void k_agg(const float* __restrict__ bias, const void* __restrict__ batch) {
    int node = (blockIdx.x * blockDim.x + threadIdx.x) >> 5;
    int lane = threadIdx.x & 31;
    if (node >= NN) return;
    int beg = g_rowptr[node];
    int end = g_rowptr[node + 1];
    int co = lane * 4;
    const __half* tb = (const __half*)g_th;

    float ax = 0.f, ay = 0.f, az = 0.f, aw = 0.f;

    int j = beg;
    for (; (j & 3) && j < end; j++) {
        int s = g_edge_src[j];
        uint2 r = *(const uint2*)(tb + (size_t)s * CH + co);
        float2 a = __half22float2(*(__half2*)&r.x);
        float2 b2 = __half22float2(*(__half2*)&r.y);
        ax += a.x; ay += a.y; az += b2.x; aw += b2.y;
    }
    for (; j + 8 <= end; j += 8) {
        int4 s0 = *(const int4*)&g_edge_src[j];
        int4 s1 = *(const int4*)&g_edge_src[j + 4];
        uint2 r0 = *(const uint2*)(tb + (size_t)s0.x * CH + co);
        uint2 r1 = *(const uint2*)(tb + (size_t)s0.y * CH + co);
        uint2 r2 = *(const uint2*)(tb + (size_t)s0.z * CH + co);
        uint2 r3 = *(const uint2*)(tb + (size_t)s0.w * CH + co);
        uint2 r4 = *(const uint2*)(tb + (size_t)s1.x * CH + co);
        uint2 r5 = *(const uint2*)(tb + (size_t)s1.y * CH + co);
        uint2 r6 = *(const uint2*)(tb + (size_t)s1.z * CH + co);
        uint2 r7 = *(const uint2*)(tb + (size_t)s1.w * CH + co);
        float2 a0 = __half22float2(*(__half2*)&r0.x), b0 = __half22float2(*(__half2*)&r0.y);
        float2 a1 = __half22float2(*(__half2*)&r1.x), b1 = __half22float2(*(__half2*)&r1.y);
        float2 a2 = __half22float2(*(__half2*)&r2.x), b2 = __half22float2(*(__half2*)&r2.y);
        float2 a3 = __half22float2(*(__half2*)&r3.x), b3 = __half22float2(*(__half2*)&r3.y);
        float2 a4 = __half22float2(*(__half2*)&r4.x), b4 = __half22float2(*(__half2*)&r4.y);
        float2 a5 = __half22float2(*(__half2*)&r5.x), b5 = __half22float2(*(__half2*)&r5.y);
        float2 a6 = __half22float2(*(__half2*)&r6.x), b6 = __half22float2(*(__half2*)&r6.y);
        float2 a7 = __half22float2(*(__half2*)&r7.x), b7 = __half22float2(*(__half2*)&r7.y);
        ax += a0.x + a1.x + a2.x + a3.x + a4.x + a5.x + a6.x + a7.x;
        ay += a0.y + a1.y + a2.y + a3.y + a4.y + a5.y + a6.y + a7.y;
        az += b0.x + b1.x + b2.x + b3.x + b4.x + b5.x + b6.x + b7.x;
        aw += b0.y + b1.y + b2.y + b3.y + b4.y + b5.y + b6.y + b7.y;
    }
    for (; j < end; j++) {
        int s = g_edge_src[j];
        uint2 r = *(const uint2*)(tb + (size_t)s * CH + co);
        float2 a = __half22float2(*(__half2*)&r.x);
        float2 b2 = __half22float2(*(__half2*)&r.y);
        ax += a.x; ay += a.y; az += b2.x; aw += b2.y;
    }

    float dv = g_dinv[node];
    float4 b = *(const float4*)(bias + co);
    ax = fmaxf(fmaf(dv, ax, b.x), 0.f);
    ay = fmaxf(fmaf(dv, ay, b.y), 0.f);
    az = fmaxf(fmaf(dv, az, b.z), 0.f);
    aw = fmaxf(fmaf(dv, aw, b.w), 0.f);

    if (LAST) {
        int g = ld_idx(batch, node, g_b64);
        float* pp = g_pool + g * CH + co;
        atomicAdd(pp + 0, ax);
        atomicAdd(pp + 1, ay);
        atomicAdd(pp + 2, az);
        atomicAdd(pp + 3, aw);
    } else {
        __half2 h0 = __floats2half2_rn(ax, ay);
        __half2 h1 = __floats2half2_rn(az, aw);
        uint2 o;
        o.x = *(uint32_t*)&h0; o.y = *(uint32_t*)&h1;
        *(uint2*)((__half*)g_hh + (size_t)node * CH + co) = o;
    }
}

// ---------------- head: out[g] = dot(pool[g], head_w) + head_b --------------
__global__ void k_head(const float* __restrict__ hw, const float* __restrict__ hb,
                       float* __restrict__ out) {
    int gid = (blockIdx.x * blockDim.x + threadIdx.x) >> 5;
    int lane = threadIdx.x & 31;
    if (gid >= NG) return;
    const float* p = g_pool + gid * CH;
    float s = p[lane]      * hw[lane]
            + p[lane + 32] * hw[lane + 32]
            + p[lane + 64] * hw[lane + 64]
            + p[lane + 96] * hw[lane + 96];
    #pragma unroll
    for (int o = 16; o; o >>= 1) s += __shfl_xor_sync(0xffffffffu, s, o);
    if (lane == 0) out[gid] = s + hb[0];
}

// ---------------- launch ----------------------------------------------------
extern "C" void kernel_launch(void* const* d_in, const int* in_sizes, int n_in,
                              void* d_out, int out_size) {
    // Inputs identified by UNIQUE element counts (order-proof).
    const float* x     = nullptr;
    const void*  ei    = nullptr;
    const void*  batch = nullptr;
    const float* Ws    = nullptr;
    const float* bs    = nullptr;
    const float* hw    = nullptr;
    const float* hb    = nullptr;
    for (int i = 0; i < n_in; i++) {
        switch (in_sizes[i]) {
            case 12800000: x     = (const float*)d_in[i]; break;
            case 3200000:  ei    = d_in[i];               break;
            case 100000:   batch = d_in[i];               break;
            case 49152:    Ws    = (const float*)d_in[i]; break;
            case 384:      bs    = (const float*)d_in[i]; break;
            case 128:      hw    = (const float*)d_in[i]; break;
            case 1:        hb    = (const float*)d_in[i]; break;
            default: break;
        }
    }
    float* out = (float*)d_out;

    const int T = 256;
    int gPre = (NN + T - 1) / T;               // 391 blocks — covers NN
    int gE4 = (NE / 4 + T - 1) / T;            // 4 edges per thread
    int gGemm = (NN + GROWS - 1) / GROWS;      // 1563 blocks of 128 threads
    int gAgg = (NN + 7) / 8;                   // 8 warps per 256-thread block

    k_pre<<<gPre, T>>>(Ws, (const int*)ei, (const int*)batch);
    k_degree<<<gE4, T>>>(ei);
    k_scan_all<<<NB_SCAN, SCAN_T>>>();        // produces g_dinv (needed by GEMM epi)
    k_fill<<<gE4, T>>>(ei);

    // layer 0
    k_gemm_tc<<<gGemm, 128>>>(x, 0);
    k_agg<false><<<gAgg, T>>>(bs + 0 * CH, batch);
    // layer 1 (A=nullptr -> read g_hh fp16)
    k_gemm_tc<<<gGemm, 128>>>(nullptr, 1);
    k_agg<false><<<gAgg, T>>>(bs + 1 * CH, batch);
    // layer 2: aggregation feeds ONLY the pool (dead g_hh store removed)
    k_gemm_tc<<<gGemm, 128>>>(nullptr, 2);
    k_agg<true><<<gAgg, T>>>(bs + 2 * CH, batch);

    // readout head
    k_head<<<(NG * 32 + T - 1) / T, T>>>(hw, hb, out);
}

// round 16
// speedup vs baseline: 1.0053x; 1.0053x over previous
#include <cuda_runtime.h>
#include <cuda_fp16.h>
#include <cstdint>

// Problem constants (fixed by the reference)
#define NN   100000
#define NE   1600000
#define CH   128
#define NG   512
#define TOT  (NE + NN)          // edges + self loops
#define SCAN_T 1024
#define NB_SCAN ((NN + SCAN_T - 1) / SCAN_T)   // 98
#define GROWS 64                 // GEMM rows per block
#define NWFRAG (3 * 8 * 16 * 32) // layers x kc(8) x nt(16) x lanes(32)

// ---------------- scratch (static __device__ allocations; allowed) ----------
__device__ __half g_th[(size_t)NN * CH];   // post-GEMM features, dinv-prescaled (fp16)
__device__ __half g_hh[(size_t)NN * CH];   // post-aggregation features (fp16)
__device__ float g_pool[NG * CH];          // global_add_pool accumulator
__device__ float g_dinv[NN];
__device__ int   g_cnt[NN];
__device__ int   g_rowptr[NN + 1];
__device__ int   g_rank[NE];               // per-edge rank within its dst (from degree pass)
__device__ int   g_edge_src[TOT];          // src index only (dinv factored out)
__device__ int   g_scan_flag[NB_SCAN];     // 0=none, 1=aggregate, 2=inclusive
__device__ int   g_agg_val[NB_SCAN];
__device__ int   g_inc_val[NB_SCAN];
__device__ int   g_ei64;                   // 1 if edge_index is int64, else int32
__device__ int   g_b64;                    // 1 if batch is int64, else int32
// B fragments for mma.m16n8k16.f16 in register order:
// index = ((layer*8 + kc)*16 + nt)*32 + lane -> uint2 {b0(half2), b1(half2)}
__device__ uint2 g_wfrag[NWFRAG];

// ---------------- dtype-agnostic index load ---------------------------------
__device__ __forceinline__ int ld_idx(const void* __restrict__ p, int i, int is64) {
    if (is64) return (int)((const long long*)p)[i];
    return ((const int*)p)[i];
}

// ---------------- fused pre kernel -------------------------------------------
__global__ void k_pre(const float* __restrict__ Ws,
                      const int* __restrict__ ei32,
                      const int* __restrict__ b32) {
    int idx = blockIdx.x * blockDim.x + threadIdx.x;

    if (idx < NN) g_cnt[idx] = 1;            // self loop contributes 1 to degree
    if (idx < NG * CH) g_pool[idx] = 0.0f;
    if (idx < NB_SCAN) g_scan_flag[idx] = 0;

    if (idx < NWFRAG) {
        int lane = idx & 31;
        int nt   = (idx >> 5) & 15;
        int kc   = (idx >> 9) & 7;
        int l    = idx >> 12;
        const float* W = Ws + (size_t)l * CH * CH;
        int tg = lane & 3, g = lane >> 2;
        int k0 = kc * 16 + 2 * tg;
        int n  = nt * 8 + g;
        __half2 b0 = __floats2half2_rn(W[(size_t)k0 * CH + n],
                                       W[(size_t)(k0 + 1) * CH + n]);
        __half2 b1 = __floats2half2_rn(W[(size_t)(k0 + 8) * CH + n],
                                       W[(size_t)(k0 + 9) * CH + n]);
        g_wfrag[idx] = make_uint2(*(uint32_t*)&b0, *(uint32_t*)&b1);
    }

    // dtype detection: int64 of small values has zero odd 32-bit words.
    if (blockIdx.x == 0 && threadIdx.x < 64) {
        int w = threadIdx.x >> 5, l = threadIdx.x & 31;
        int nz = 0;
        if (w == 0) {
            #pragma unroll
            for (int k = 0; k < 2; k++)
                nz |= (ei32[2 * (l * 2 + k) + 1] != 0);
            unsigned m = __ballot_sync(0xffffffffu, nz);
            if (l == 0) g_ei64 = (m == 0u);
        } else {
            #pragma unroll
            for (int k = 0; k < 2; k++)
                nz |= (b32[2 * (25000 + l * 2 + k) + 1] != 0);
            unsigned m = __ballot_sync(0xffffffffu, nz);
            if (l == 0) g_b64 = (m == 0u);
        }
    }
}

// ---------------- degree count + per-edge rank --------------------------------
// rank[e] = old count (starts at 1 because of the self loop at slot 0)
__global__ void k_degree(const void* __restrict__ ei) {
    int base = (blockIdx.x * blockDim.x + threadIdx.x) * 4;
    if (base >= NE) return;
    int is64 = g_ei64;
    if (base + 4 <= NE) {
        int d0, d1, d2, d3;
        if (is64) {
            const longlong2* p = (const longlong2*)((const long long*)ei + NE + base);
            longlong2 v0 = p[0], v1 = p[1];
            d0 = (int)v0.x; d1 = (int)v0.y; d2 = (int)v1.x; d3 = (int)v1.y;
        } else {
            int4 v = *(const int4*)((const int*)ei + NE + base);
            d0 = v.x; d1 = v.y; d2 = v.z; d3 = v.w;
        }
        int r0 = atomicAdd(&g_cnt[d0], 1);
        int r1 = atomicAdd(&g_cnt[d1], 1);
        int r2 = atomicAdd(&g_cnt[d2], 1);
        int r3 = atomicAdd(&g_cnt[d3], 1);
        *(int4*)&g_rank[base] = make_int4(r0, r1, r2, r3);
    } else {
        for (int e = base; e < NE; e++)
            g_rank[e] = atomicAdd(&g_cnt[ld_idx(ei, NE + e, is64)], 1);
    }
}

// ---------------- single-pass scan (decoupled lookback) ----------------------
__global__ __launch_bounds__(SCAN_T)
void k_scan_all() {
    __shared__ int ws[32];
    __shared__ int s_prefix;
    int tid = threadIdx.x, b = blockIdx.x;
    int i = b * SCAN_T + tid;
    int v = (i < NN) ? g_cnt[i] : 0;
    float dinv = rsqrtf((float)v);
    if (i < NN) g_dinv[i] = dinv;

    int lane = tid & 31, wid = tid >> 5;
    int x = v;
    #pragma unroll
    for (int o = 1; o < 32; o <<= 1) {
        int y = __shfl_up_sync(0xffffffffu, x, o);
        if (lane >= o) x += y;
    }
    if (lane == 31) ws[wid] = x;
    __syncthreads();
    if (wid == 0) {
        int s = ws[lane];
        #pragma unroll
        for (int o = 1; o < 32; o <<= 1) {
            int y = __shfl_up_sync(0xffffffffu, s, o);
            if (lane >= o) s += y;
        }
        ws[lane] = s;
    }
    __syncthreads();
    int off = wid ? ws[wid - 1] : 0;
    int incl = x + off;                 // inclusive within block
    int total = ws[31];                 // block aggregate

    if (b == 0) {
        if (tid == 0) {
            g_inc_val[0] = total;
            __threadfence();
            atomicExch(&g_scan_flag[0], 2);
            s_prefix = 0;
        }
    } else {
        if (tid == 0) {
            g_agg_val[b] = total;
            __threadfence();
            atomicExch(&g_scan_flag[b], 1);
        }
        if (tid < 32) {                 // warp-parallel lookback
            int sum = 0, p = b - 1;
            while (true) {
                int idxp = p - lane;
                int f = 2, vv = 0;
                if (idxp >= 0) {
                    f = atomicAdd(&g_scan_flag[idxp], 0);
                    if (f == 2)      vv = atomicAdd(&g_inc_val[idxp], 0);
                    else if (f == 1) vv = atomicAdd(&g_agg_val[idxp], 0);
                }
                unsigned pm = __ballot_sync(0xffffffffu, f == 2);
                unsigned am = __ballot_sync(0xffffffffu, f >= 1);
                if (pm) {
                    int L = __ffs(pm) - 1;
                    unsigned below = (L == 0) ? 0u : ((1u << L) - 1u);
                    if ((am & below) == below) {
                        int c = (lane <= L) ? vv : 0;
                        #pragma unroll
                        for (int o = 16; o; o >>= 1)
                            c += __shfl_xor_sync(0xffffffffu, c, o);
                        sum += c;
                        break;
                    }
                } else if (am == 0xffffffffu) {
                    int c = vv;
                    #pragma unroll
                    for (int o = 16; o; o >>= 1)
                        c += __shfl_xor_sync(0xffffffffu, c, o);
                    sum += c;
                    p -= 32;
                }
            }
            if (lane == 0) {
                s_prefix = sum;
                g_inc_val[b] = sum + total;
                __threadfence();
                atomicExch(&g_scan_flag[b], 2);
            }
        }
    }
    __syncthreads();

    int prefix = s_prefix;
    if (i < NN) {
        int rp = prefix + incl - v;     // exclusive global prefix
        g_rowptr[i] = rp;
        g_edge_src[rp] = i;             // self-loop edge: src = i (slot 0 = rank 0)
    }
    if (i == 0) g_rowptr[NN] = TOT;
}

// ---------------- CSR fill: atomic-free via precomputed ranks ----------------
__global__ void k_fill(const void* __restrict__ ei) {
    int base = (blockIdx.x * blockDim.x + threadIdx.x) * 4;
    if (base >= NE) return;
    int is64 = g_ei64;
    if (base + 4 <= NE) {
        int s0, s1, s2, s3, d0, d1, d2, d3;
        if (is64) {
            const longlong2* ps = (const longlong2*)((const long long*)ei + base);
            const longlong2* pd = (const longlong2*)((const long long*)ei + NE + base);
            longlong2 u0 = ps[0], u1 = ps[1];
            longlong2 v0 = pd[0], v1 = pd[1];
            s0 = (int)u0.x; s1 = (int)u0.y; s2 = (int)u1.x; s3 = (int)u1.y;
            d0 = (int)v0.x; d1 = (int)v0.y; d2 = (int)v1.x; d3 = (int)v1.y;
        } else {
            int4 u = *(const int4*)((const int*)ei + base);
            int4 v = *(const int4*)((const int*)ei + NE + base);
            s0 = u.x; s1 = u.y; s2 = u.z; s3 = u.w;
            d0 = v.x; d1 = v.y; d2 = v.z; d3 = v.w;
        }
        int4 rk = *(const int4*)&g_rank[base];
        g_edge_src[g_rowptr[d0] + rk.x] = s0;
        g_edge_src[g_rowptr[d1] + rk.y] = s1;
        g_edge_src[g_rowptr[d2] + rk.z] = s2;
        g_edge_src[g_rowptr[d3] + rk.w] = s3;
    } else {
        for (int e = base; e < NE; e++) {
            int s = ld_idx(ei, e, is64);
            int d = ld_idx(ei, NE + e, is64);
            g_edge_src[g_rowptr[d] + g_rank[e]] = s;
        }
    }
}

// ---------------- GEMM via fp16 tensor cores (m16n8k16, fp32 accum) ----------
// g_th[N,128] = fp16(dinv_row * (A[N,128] @ W[128,128])); A==nullptr -> g_hh.
__global__ __launch_bounds__(128)
void k_gemm_tc(const float* __restrict__ A_, int layer) {
    __shared__ __half sA[GROWS][136];
    int tid = threadIdx.x, wid = tid >> 5, lane = tid & 31;
    int row0 = blockIdx.x * GROWS;

    if (A_ != nullptr) {
        #pragma unroll
        for (int i = tid; i < GROWS * 16; i += 128) {
            int r = i >> 4, c8 = (i & 15) << 3;
            int gr = row0 + r;
            __half2 h0, h1, h2, h3;
            if (gr < NN) {
                const float* src = A_ + (size_t)gr * CH + c8;
                float4 v0 = *(const float4*)(src);
                float4 v1 = *(const float4*)(src + 4);
                h0 = __floats2half2_rn(v0.x, v0.y);
                h1 = __floats2half2_rn(v0.z, v0.w);
                h2 = __floats2half2_rn(v1.x, v1.y);
                h3 = __floats2half2_rn(v1.z, v1.w);
            } else {
                h0 = h1 = h2 = h3 = __floats2half2_rn(0.f, 0.f);
            }
            uint4 u;
            u.x = *(uint32_t*)&h0; u.y = *(uint32_t*)&h1;
            u.z = *(uint32_t*)&h2; u.w = *(uint32_t*)&h3;
            *(uint4*)&sA[r][c8] = u;
        }
    } else {
        const __half* hb = (const __half*)g_hh;
        #pragma unroll
        for (int i = tid; i < GROWS * 16; i += 128) {
            int r = i >> 4, c8 = (i & 15) << 3;
            int gr = row0 + r;
            uint4 u = make_uint4(0, 0, 0, 0);
            if (gr < NN) u = *(const uint4*)(hb + (size_t)gr * CH + c8);
            *(uint4*)&sA[r][c8] = u;
        }
    }
    __syncthreads();

    int mrow = wid * 16;
    int g  = lane >> 2;        // group id 0..7
    int tg = lane & 3;         // thread-in-group

    float acc[16][4];
    #pragma unroll
    for (int nt = 0; nt < 16; nt++)
        #pragma unroll
        for (int j = 0; j < 4; j++) acc[nt][j] = 0.f;

    const uint2* __restrict__ wbase = g_wfrag + ((size_t)layer * 128) * 32 + lane;

    #pragma unroll
    for (int kc = 0; kc < 8; kc++) {
        int k0 = kc * 16 + 2 * tg;
        uint32_t a0 = *(const uint32_t*)&sA[mrow + g][k0];
        uint32_t a1 = *(const uint32_t*)&sA[mrow + g + 8][k0];
        uint32_t a2 = *(const uint32_t*)&sA[mrow + g][k0 + 8];
        uint32_t a3 = *(const uint32_t*)&sA[mrow + g + 8][k0 + 8];
        const uint2* wk = wbase + (size_t)(kc * 16) * 32;
        #pragma unroll
        for (int nt = 0; nt < 16; nt++) {
            uint2 b = wk[(size_t)nt * 32];
            asm volatile(
                "mma.sync.aligned.m16n8k16.row.col.f32.f16.f16.f32 "
                "{%0,%1,%2,%3}, {%4,%5,%6,%7}, {%8,%9}, {%0,%1,%2,%3};"
                : "+f"(acc[nt][0]), "+f"(acc[nt][1]),
                  "+f"(acc[nt][2]), "+f"(acc[nt][3])
                : "r"(a0), "r"(a1), "r"(a2), "r"(a3), "r"(b.x), "r"(b.y));
        }
    }

    // epilogue: scale rows by dinv and store fp16
    int gr0 = row0 + mrow + g;
    int gr1 = gr0 + 8;
    float dv0 = (gr0 < NN) ? g_dinv[gr0] : 0.f;
    float dv1 = (gr1 < NN) ? g_dinv[gr1] : 0.f;
    #pragma unroll
    for (int nt = 0; nt < 16; nt++) {
        int col = nt * 8 + 2 * tg;
        if (gr0 < NN)
            *(__half2*)&g_th[(size_t)gr0 * CH + col] =
                __floats2half2_rn(dv0 * acc[nt][0], dv0 * acc[nt][1]);
        if (gr1 < NN)
            *(__half2*)&g_th[(size_t)gr1 * CH + col] =
                __floats2half2_rn(dv1 * acc[nt][2], dv1 * acc[nt][3]);
    }
}

// ---------------- aggregation: h[i] = ReLU(dinv_i * sum_j t'[src_j] + b) ----
template <bool LAST>
__global__ __launch_bounds__(256)
void k_agg(const float* __restrict__ bias, const void* __restrict__ batch) {
    int node = (blockIdx.x * blockDim.x + threadIdx.x) >> 5;
    int lane = threadIdx.x & 31;
    if (node >= NN) return;
    int beg = g_rowptr[node];
    int end = g_rowptr[node + 1];
    int co = lane * 4;
    const __half* tb = (const __half*)g_th;

    float ax = 0.f, ay = 0.f, az = 0.f, aw = 0.f;

    int j = beg;
    for (; (j & 3) && j < end; j++) {
        int s = g_edge_src[j];
        uint2 r = *(const uint2*)(tb + (size_t)s * CH + co);
        float2 a = __half22float2(*(__half2*)&r.x);
        float2 b2 = __half22float2(*(__half2*)&r.y);
        ax += a.x; ay += a.y; az += b2.x; aw += b2.y;
    }
    for (; j + 8 <= end; j += 8) {
        int4 s0 = *(const int4*)&g_edge_src[j];
        int4 s1 = *(const int4*)&g_edge_src[j + 4];
        uint2 r0 = *(const uint2*)(tb + (size_t)s0.x * CH + co);
        uint2 r1 = *(const uint2*)(tb + (size_t)s0.y * CH + co);
        uint2 r2 = *(const uint2*)(tb + (size_t)s0.z * CH + co);
        uint2 r3 = *(const uint2*)(tb + (size_t)s0.w * CH + co);
        uint2 r4 = *(const uint2*)(tb + (size_t)s1.x * CH + co);
        uint2 r5 = *(const uint2*)(tb + (size_t)s1.y * CH + co);
        uint2 r6 = *(const uint2*)(tb + (size_t)s1.z * CH + co);
        uint2 r7 = *(const uint2*)(tb + (size_t)s1.w * CH + co);
        float2 a0 = __half22float2(*(__half2*)&r0.x), b0 = __half22float2(*(__half2*)&r0.y);
        float2 a1 = __half22float2(*(__half2*)&r1.x), b1 = __half22float2(*(__half2*)&r1.y);
        float2 a2 = __half22float2(*(__half2*)&r2.x), b2 = __half22float2(*(__half2*)&r2.y);
        float2 a3 = __half22float2(*(__half2*)&r3.x), b3 = __half22float2(*(__half2*)&r3.y);
        float2 a4 = __half22float2(*(__half2*)&r4.x), b4 = __half22float2(*(__half2*)&r4.y);
        float2 a5 = __half22float2(*(__half2*)&r5.x), b5 = __half22float2(*(__half2*)&r5.y);
        float2 a6 = __half22float2(*(__half2*)&r6.x), b6 = __half22float2(*(__half2*)&r6.y);
        float2 a7 = __half22float2(*(__half2*)&r7.x), b7 = __half22float2(*(__half2*)&r7.y);
        ax += a0.x + a1.x + a2.x + a3.x + a4.x + a5.x + a6.x + a7.x;
        ay += a0.y + a1.y + a2.y + a3.y + a4.y + a5.y + a6.y + a7.y;
        az += b0.x + b1.x + b2.x + b3.x + b4.x + b5.x + b6.x + b7.x;
        aw += b0.y + b1.y + b2.y + b3.y + b4.y + b5.y + b6.y + b7.y;
    }
    for (; j < end; j++) {
        int s = g_edge_src[j];
        uint2 r = *(const uint2*)(tb + (size_t)s * CH + co);
        float2 a = __half22float2(*(__half2*)&r.x);
        float2 b2 = __half22float2(*(__half2*)&r.y);
        ax += a.x; ay += a.y; az += b2.x; aw += b2.y;
    }

    float dv = g_dinv[node];
    float4 b = *(const float4*)(bias + co);
    ax = fmaxf(fmaf(dv, ax, b.x), 0.f);
    ay = fmaxf(fmaf(dv, ay, b.y), 0.f);
    az = fmaxf(fmaf(dv, az, b.z), 0.f);
    aw = fmaxf(fmaf(dv, aw, b.w), 0.f);

    if (LAST) {
        int g = ld_idx(batch, node, g_b64);
        float* pp = g_pool + g * CH + co;
        atomicAdd(pp + 0, ax);
        atomicAdd(pp + 1, ay);
        atomicAdd(pp + 2, az);
        atomicAdd(pp + 3, aw);
    } else {
        __half2 h0 = __floats2half2_rn(ax, ay);
        __half2 h1 = __floats2half2_rn(az, aw);
        uint2 o;
        o.x = *(uint32_t*)&h0; o.y = *(uint32_t*)&h1;
        *(uint2*)((__half*)g_hh + (size_t)node * CH + co) = o;
    }
}

// ---------------- head: out[g] = dot(pool[g], head_w) + head_b --------------
__global__ void k_head(const float* __restrict__ hw, const float* __restrict__ hb,
                       float* __restrict__ out) {
    int gid = (blockIdx.x * blockDim.x + threadIdx.x) >> 5;
    int lane = threadIdx.x & 31;
    if (gid >= NG) return;
    const float* p = g_pool + gid * CH;
    float s = p[lane]      * hw[lane]
            + p[lane + 32] * hw[lane + 32]
            + p[lane + 64] * hw[lane + 64]
            + p[lane + 96] * hw[lane + 96];
    #pragma unroll
    for (int o = 16; o; o >>= 1) s += __shfl_xor_sync(0xffffffffu, s, o);
    if (lane == 0) out[gid] = s + hb[0];
}

// ---------------- launch ----------------------------------------------------
extern "C" void kernel_launch(void* const* d_in, const int* in_sizes, int n_in,
                              void* d_out, int out_size) {
    // Inputs identified by UNIQUE element counts (order-proof).
    const float* x     = nullptr;
    const void*  ei    = nullptr;
    const void*  batch = nullptr;
    const float* Ws    = nullptr;
    const float* bs    = nullptr;
    const float* hw    = nullptr;
    const float* hb    = nullptr;
    for (int i = 0; i < n_in; i++) {
        switch (in_sizes[i]) {
            case 12800000: x     = (const float*)d_in[i]; break;
            case 3200000:  ei    = d_in[i];               break;
            case 100000:   batch = d_in[i];               break;
            case 49152:    Ws    = (const float*)d_in[i]; break;
            case 384:      bs    = (const float*)d_in[i]; break;
            case 128:      hw    = (const float*)d_in[i]; break;
            case 1:        hb    = (const float*)d_in[i]; break;
            default: break;
        }
    }
    float* out = (float*)d_out;

    const int T = 256;
    int gPre = (NN + T - 1) / T;               // 391 blocks — covers NN
    int gE4 = (NE / 4 + T - 1) / T;            // 4 edges per thread
    int gGemm = (NN + GROWS - 1) / GROWS;      // 1563 blocks of 128 threads
    int gAgg = (NN + 7) / 8;                   // 8 warps per 256-thread block

    k_pre<<<gPre, T>>>(Ws, (const int*)ei, (const int*)batch);
    k_degree<<<gE4, T>>>(ei);
    k_scan_all<<<NB_SCAN, SCAN_T>>>();        // produces g_dinv + rowptr + self loops
    k_fill<<<gE4, T>>>(ei);                   // atomic-free: rowptr[d] + rank[e]

    // layer 0
    k_gemm_tc<<<gGemm, 128>>>(x, 0);
    k_agg<false><<<gAgg, T>>>(bs + 0 * CH, batch);
    // layer 1 (A=nullptr -> read g_hh fp16)
    k_gemm_tc<<<gGemm, 128>>>(nullptr, 1);
    k_agg<false><<<gAgg, T>>>(bs + 1 * CH, batch);
    // layer 2: aggregation feeds ONLY the pool (dead g_hh store removed)
    k_gemm_tc<<<gGemm, 128>>>(nullptr, 2);
    k_agg<true><<<gAgg, T>>>(bs + 2 * CH, batch);

    // readout head
    k_head<<<(NG * 32 + T - 1) / T, T>>>(hw, hb, out);
}